// round 14
// baseline (speedup 1.0000x reference)
#include <cuda_runtime.h>
#include <cuda_fp16.h>
#include <math.h>
#include <float.h>
#include <stdint.h>

// ---------------------------------------------------------------------------
// BottleneckBit via ldmatrix + mma.sync fp16 (base sm_103 target).
// R14: conv2 window-reuse via padded spatial layout.
//   u1 stored padded: np = b*256 + (r+1)*16 + (c+1), zero pad ring (device
//   global zero-init, pads never written). conv2 loads a 192-row window per
//   k-chunk ONCE into smem and runs all 9 taps from it (B global traffic /9,
//   8 of 9 chunks have no global-load wait). Taps never cross image blocks.
// gemm1/gemm3/prep unchanged from R13 except gemm1's epilogue writes padded.
// ---------------------------------------------------------------------------

#define BATCH 64
#define CIN   1024
#define WIDTH 256
#define COUT  1024
#define HW    196
#define NC    12544            // compact columns = 64*196 = 98*128
#define NPTOT 16384            // padded columns  = 64*256 = 128*128
#define U1MARGIN 32

#define PITCH 144              // smem row: 64 fp16 (128B) + 16B pad
#define ATILEB (64*PITCH)      // 9216  (A: 64 rows)
#define BTILEB (128*PITCH)     // 18432 (B: 128 rows)
#define STAGEB (ATILEB+BTILEB) // 27648
#define SMEMB (2*STAGEB)       // 55296 (gemm1/gemm3)

#define WTILEB (192*PITCH)     // 27648 conv2 window (192 rows)
#define C2SMEM (2*WTILEB + 2*ATILEB)   // 73728

#define EPIPITCH 72            // halves per row (64 + 8 pad); 144B

__device__ __half g_w1h[WIDTH*CIN];         // [o][c]
__device__ __half g_w2h[9*WIDTH*WIDTH];     // [tap][o][c]
__device__ __half g_w3h[COUT*WIDTH];        // [o][c]
__device__ float g_scale1[WIDTH],  g_bias1[WIDTH];
__device__ float g_scale2[WIDTH],  g_bias2[WIDTH];
__device__ float g_scale3[COUT],   g_bias3[COUT];
__device__ __half g_xs[(size_t)NC*CIN];     // [n][c]
__device__ __half g_u1p[(size_t)(NPTOT + 2*U1MARGIN)*WIDTH]; // padded u1
__device__ __half g_u2[(size_t)NC*WIDTH];   // [n][c] compact

// ---------------------------------------------------------------------------
__device__ __forceinline__ uint32_t smem_u32(const void* p) {
    uint32_t a;
    asm("{ .reg .u64 t; cvta.to.shared.u64 t, %1; cvt.u32.u64 %0, t; }"
        : "=r"(a) : "l"(p));
    return a;
}
__device__ __forceinline__ void cpa16(uint32_t dst, const void* src) {
    asm volatile("cp.async.cg.shared.global [%0], [%1], 16;" :: "r"(dst), "l"(src));
}
#define CP_COMMIT() asm volatile("cp.async.commit_group;" ::: "memory")
#define CP_WAIT0()  asm volatile("cp.async.wait_group 0;" ::: "memory")

__device__ __forceinline__ void ldmA(uint32_t* a, uint32_t addr) {
    asm volatile("ldmatrix.sync.aligned.m8n8.x4.shared.b16 {%0,%1,%2,%3}, [%4];"
                 : "=r"(a[0]), "=r"(a[1]), "=r"(a[2]), "=r"(a[3]) : "r"(addr));
}
__device__ __forceinline__ void ldmB(uint32_t* b, uint32_t addr) {
    asm volatile("ldmatrix.sync.aligned.m8n8.x2.shared.b16 {%0,%1}, [%2];"
                 : "=r"(b[0]), "=r"(b[1]) : "r"(addr));
}
__device__ __forceinline__ void mma16816(float* d, const uint32_t* a, const uint32_t* b) {
    asm volatile("mma.sync.aligned.m16n8k16.row.col.f32.f16.f16.f32 "
                 "{%0,%1,%2,%3}, {%4,%5,%6,%7}, {%8,%9}, {%0,%1,%2,%3};"
                 : "+f"(d[0]), "+f"(d[1]), "+f"(d[2]), "+f"(d[3])
                 : "r"(a[0]), "r"(a[1]), "r"(a[2]), "r"(a[3]), "r"(b[0]), "r"(b[1]));
}
__device__ __forceinline__ float silu_f(float x) { return x / (1.0f + expf(-x)); }

// one 64x128x64 chunk: warps 2(M) x 4(N), warp tile 32x32
__device__ __forceinline__ void mma_chunk(uint32_t Abuf, uint32_t Bbuf,
                                          int wm, int wn, int lane,
                                          float acc[2][4][4])
{
    const uint32_t aRowSel = (uint32_t)(lane & 15) * PITCH + (uint32_t)(lane >> 4) * 16;
    const uint32_t bRowSel = (uint32_t)(lane & 7)  * PITCH + (uint32_t)((lane >> 3) & 1) * 16;
#pragma unroll
    for (int ks = 0; ks < 4; ks++) {
        uint32_t afr[2][4];
#pragma unroll
        for (int mf = 0; mf < 2; mf++)
            ldmA(afr[mf], Abuf + (uint32_t)(wm * 32 + mf * 16) * PITCH + ks * 32 + aRowSel);
        uint32_t bfr[4][2];
#pragma unroll
        for (int nf = 0; nf < 4; nf++)
            ldmB(bfr[nf], Bbuf + (uint32_t)(wn * 32 + nf * 8) * PITCH + ks * 32 + bRowSel);
#pragma unroll
        for (int mf = 0; mf < 2; mf++)
#pragma unroll
            for (int nf = 0; nf < 4; nf++)
                mma16816(acc[mf][nf], afr[mf], bfr[nf]);
    }
}

// transpose phase: acc -> st[n(128)][o(64)] half tile (with scale/bias/silu)
__device__ __forceinline__ void epi_transpose(__half* st, int wm, int wn, int lane,
                                              int mbase,
                                              const float* scale, const float* bias,
                                              float acc[2][4][4])
{
#pragma unroll
    for (int mf = 0; mf < 2; mf++) {
#pragma unroll
        for (int half = 0; half < 2; half++) {
            const int ol = wm * 32 + mf * 16 + (lane >> 2) + half * 8;
            const float sc = scale[mbase + ol], bi = bias[mbase + ol];
#pragma unroll
            for (int nf = 0; nf < 4; nf++) {
#pragma unroll
                for (int cc = 0; cc < 2; cc++) {
                    int nrow = wn * 32 + nf * 8 + (lane & 3) * 2 + cc;
                    float sv = silu_f(sc * acc[mf][nf][half * 2 + cc] + bi);
                    st[nrow * EPIPITCH + ol] = __float2half_rn(sv);
                }
            }
        }
    }
}

// ---------------------------------------------------------------------------
// prep: blocks [0,1536) quantize weights, blocks [1536,2560) convert x->fp16.
// ---------------------------------------------------------------------------
__global__ void __launch_bounds__(256) prep_kernel(
    const float* __restrict__ x,
    const float* __restrict__ w1, const float* __restrict__ b1,
    const float* __restrict__ g1, const float* __restrict__ be1,
    const float* __restrict__ m1, const float* __restrict__ v1,
    const float* __restrict__ w2, const float* __restrict__ b2,
    const float* __restrict__ g2, const float* __restrict__ be2,
    const float* __restrict__ m2, const float* __restrict__ v2,
    const float* __restrict__ w3, const float* __restrict__ b3,
    const float* __restrict__ g3, const float* __restrict__ be3,
    const float* __restrict__ m3, const float* __restrict__ v3)
{
    const int blk = blockIdx.x;
    const int tid = threadIdx.x;

    if (blk >= 1536) {
        // ---- xconv part ----
        extern __shared__ float s[];
        const int idx = blk - 1536;
        const int b = idx >> 4, cb = idx & 15;
        const float* xp = x + ((size_t)b * CIN + cb * 64) * HW;
        for (int i = tid; i < 64 * HW; i += 256) {
            int ci = i / HW, p = i - ci * HW;
            s[ci * 197 + p] = xp[(size_t)ci * HW + p];
        }
        __syncthreads();
        const int coff = tid & 63;
        for (int p = tid >> 6; p < HW; p += 4) {
            int n = b * HW + p;
            g_xs[(size_t)n * CIN + cb * 64 + coff] = __float2half_rn(s[coff * 197 + p]);
        }
        return;
    }

    // ---- quant part ----
    __shared__ int scnt0, scnt1;
    int which, o, K;
    const float *w, *bc, *g, *be, *m, *v;
    if (blk < 256)      { which = 1; o = blk;       K = 1024; w = w1; bc = b1; g = g1; be = be1; m = m1; v = v1; }
    else if (blk < 512) { which = 2; o = blk - 256; K = 2304; w = w2; bc = b2; g = g2; be = be2; m = m2; v = v2; }
    else                { which = 3; o = blk - 512; K = 256;  w = w3; bc = b3; g = g3; be = be3; m = m3; v = v3; }

    const float* wrow = w + (size_t)o * K;
    uint32_t vals[9];
    const int nv = (K + 255) / 256;
    for (int j = 0; j < nv; j++) {
        int idx = tid + j * 256;
        vals[j] = (idx < K) ? __float_as_uint(fabsf(wrow[idx])) : 0xffffffffu;
    }

    const int k0 = K / 2 - 1, k1 = K / 2;
    uint32_t lo0 = 0, hi0 = 0x7f7fffffu, lo1 = 0, hi1 = 0x7f7fffffu;
    while (lo0 < hi0 || lo1 < hi1) {
        uint32_t mid0 = lo0 + ((hi0 - lo0) >> 1);
        uint32_t mid1 = lo1 + ((hi1 - lo1) >> 1);
        __syncthreads();
        if (tid == 0) { scnt0 = 0; scnt1 = 0; }
        __syncthreads();
        int c0 = 0, c1 = 0;
        for (int j = 0; j < nv; j++) {
            c0 += (vals[j] <= mid0) ? 1 : 0;
            c1 += (vals[j] <= mid1) ? 1 : 0;
        }
#pragma unroll
        for (int off = 16; off; off >>= 1) {
            c0 += __shfl_down_sync(~0u, c0, off);
            c1 += __shfl_down_sync(~0u, c1, off);
        }
        if ((tid & 31) == 0) { atomicAdd(&scnt0, c0); atomicAdd(&scnt1, c1); }
        __syncthreads();
        if (lo0 < hi0) { if (scnt0 >= k0 + 1) hi0 = mid0; else lo0 = mid0 + 1; }
        if (lo1 < hi1) { if (scnt1 >= k1 + 1) hi1 = mid1; else lo1 = mid1 + 1; }
    }
    const float med = 0.5f * (__uint_as_float(lo0) + __uint_as_float(lo1));
    const float sc = fmaxf(med, 1e-8f);
    const float alpha = g[o] / sqrtf(v[o] + 1e-5f);

    for (int i = tid; i < K; i += 256) {
        float q = rintf(wrow[i] / sc);
        q = fminf(fmaxf(q, -1.0f), 1.0f);
        __half t = __float2half_rn(q);          // exact ternary
        if (which == 1)      g_w1h[(size_t)o * CIN + i] = t;
        else if (which == 3) g_w3h[(size_t)o * WIDTH + i] = t;
        else {
            int c = i / 9, tap = i - c * 9;
            g_w2h[((size_t)tap * WIDTH + o) * WIDTH + c] = t;
        }
    }
    if (tid == 0) {
        float scal = sc * alpha;
        float bias = bc[o] * alpha + be[o] - m[o] * alpha;
        if (which == 1)      { g_scale1[o] = scal; g_bias1[o] = bias; }
        else if (which == 2) { g_scale2[o] = scal; g_bias2[o] = bias; }
        else                 { g_scale3[o] = scal; g_bias3[o] = bias; }
    }
}

// ---------------------------------------------------------------------------
// GEMM1: M=256 (grid.y=4, tile 64), N=12544 (grid.x=98), K=1024, 16 chunks.
// Epilogue writes u1 in PADDED layout (+margin).
// ---------------------------------------------------------------------------
__global__ void __launch_bounds__(256, 3) gemm1_mma()
{
    extern __shared__ char smem[];
    const uint32_t sb = smem_u32(smem);
    const int tid = threadIdx.x, lane = tid & 31, wid = tid >> 5;
    const int wm = wid & 1, wn = wid >> 1;
    const int nbase = blockIdx.x * 128;
    const int mbase = blockIdx.y * 64;
    const int NCH = 16;

    const int row0 = tid >> 3, ch = tid & 7;
    const __half* srcA = g_w1h + (size_t)(mbase + row0) * CIN + ch * 8;
    const __half* srcB = g_xs + (size_t)(nbase + row0) * CIN + ch * 8;
    const uint32_t dst0 = (uint32_t)(row0 * PITCH + ch * 16);

    float acc[2][4][4];
#pragma unroll
    for (int a = 0; a < 2; a++)
#pragma unroll
        for (int b = 0; b < 4; b++)
#pragma unroll
            for (int c = 0; c < 4; c++) acc[a][b][c] = 0.0f;

    auto prefetch = [&](int i) {
        const uint32_t base = sb + (i & 1) * STAGEB;
        const int koff = i * 64;
#pragma unroll
        for (int j = 0; j < 2; j++)
            cpa16(base + dst0 + j * (32 * PITCH), srcA + koff + j * (32 * CIN));
#pragma unroll
        for (int j = 0; j < 4; j++)
            cpa16(base + ATILEB + dst0 + j * (32 * PITCH), srcB + koff + j * (32 * CIN));
        CP_COMMIT();
    };

    prefetch(0);
    for (int i = 0; i < NCH; i++) {
        CP_WAIT0();
        __syncthreads();
        if (i + 1 < NCH) prefetch(i + 1);
        const uint32_t base = sb + (i & 1) * STAGEB;
        mma_chunk(base, base + ATILEB, wm, wn, lane, acc);
    }
    // epilogue: transpose into buf0 tile (disjoint from last-chunk buf1)
    __half* st = (__half*)smem;
    epi_transpose(st, wm, wn, lane, mbase, g_scale1, g_bias1, acc);
    __syncthreads();
    {
        const int nrow = tid >> 1, off = (tid & 1) * 32;
        const int n = nbase + nrow;
        const int b = n / HW, p = n - b * HW;
        const int pr = p / 14, pc = p - pr * 14;
        const int np = b * 256 + (pr + 1) * 16 + (pc + 1);
        const uint4* s4 = (const uint4*)(st + nrow * EPIPITCH + off);
        uint4* d4 = (uint4*)(g_u1p + (size_t)(np + U1MARGIN) * WIDTH + mbase + off);
#pragma unroll
        for (int k = 0; k < 4; k++) d4[k] = s4[k];
    }
}

// ---------------------------------------------------------------------------
// CONV2 window-reuse: padded N (grid.x=128), M=256 (grid.y=4, tile 64).
// Outer loop kc (4 k-chunks): load 192-row u1p window once; inner loop 9 taps
// stream small A tiles and mma from shifted window rows. 36 chunks total.
// ---------------------------------------------------------------------------
__global__ void __launch_bounds__(256, 3) conv2_mma()
{
    extern __shared__ char smem[];
    const uint32_t sb = smem_u32(smem);
    const int tid = threadIdx.x, lane = tid & 31, wid = tid >> 5;
    const int wm = wid & 1, wn = wid >> 1;
    const int nbase = blockIdx.x * 128;   // padded np base
    const int mbase = blockIdx.y * 64;
    const uint32_t ab0 = sb + 2 * WTILEB; // A buffers after the two windows

    const int row0 = tid >> 3, ch = tid & 7;
    const uint32_t dst0 = (uint32_t)(row0 * PITCH + ch * 16);
    // window storage rows nbase..nbase+191 cover np in [nbase-32, nbase+160)
    const __half* srcW = g_u1p + (size_t)(nbase + row0) * WIDTH + ch * 8;
    const __half* srcA0 = g_w2h + (size_t)(mbase + row0) * WIDTH + ch * 8;

    auto prefW = [&](int kc) {
        const uint32_t base = sb + (kc & 1) * WTILEB;
#pragma unroll
        for (int j = 0; j < 6; j++)
            cpa16(base + dst0 + j * (32 * PITCH), srcW + kc * 64 + j * (32 * WIDTH));
        CP_COMMIT();
    };
    auto prefA = [&](int tap, int kc, int buf) {
        const uint32_t base = ab0 + buf * ATILEB;
        const __half* s = srcA0 + (size_t)tap * (WIDTH * WIDTH) + kc * 64;
#pragma unroll
        for (int j = 0; j < 2; j++)
            cpa16(base + dst0 + j * (32 * PITCH), s + j * (32 * WIDTH));
        CP_COMMIT();
    };

    float acc[2][4][4];
#pragma unroll
    for (int a = 0; a < 2; a++)
#pragma unroll
        for (int b = 0; b < 4; b++)
#pragma unroll
            for (int c = 0; c < 4; c++) acc[a][b][c] = 0.0f;

    prefW(0);
    prefA(0, 0, 0);
    int tap = 0, kc = 0;
    for (int idx = 0; idx < 36; idx++) {
        CP_WAIT0();
        __syncthreads();
        // next (tap,kc)
        int ntap = tap + 1, nkc = kc;
        if (ntap == 9) { ntap = 0; nkc = kc + 1; }
        if (tap == 0 && kc < 3) prefW(kc + 1);
        if (idx + 1 < 36) prefA(ntap, nkc, (idx + 1) & 1);
        const int shift = (tap / 3 - 1) * 16 + (tap - (tap / 3) * 3 - 1);
        const uint32_t wbuf = sb + (kc & 1) * WTILEB + (uint32_t)(32 + shift) * PITCH;
        mma_chunk(ab0 + (idx & 1) * ATILEB, wbuf, wm, wn, lane, acc);
        tap = ntap; kc = nkc;
    }

    // epilogue: transpose tile into window buf0 (last mma read wbuf1/abuf1)
    __half* st = (__half*)smem;
    epi_transpose(st, wm, wn, lane, mbase, g_scale2, g_bias2, acc);
    __syncthreads();
    {
        const int nrow = tid >> 1, off = (tid & 1) * 32;
        const int np = nbase + nrow;
        const int r = (np >> 4) & 15, c = np & 15;
        if (r >= 1 && r <= 14 && c >= 1 && c <= 14) {
            const int n = (np >> 8) * HW + (r - 1) * 14 + (c - 1);
            const uint4* s4 = (const uint4*)(st + nrow * EPIPITCH + off);
            uint4* d4 = (uint4*)(g_u2 + (size_t)n * WIDTH + mbase + off);
#pragma unroll
            for (int k = 0; k < 4; k++) d4[k] = s4[k];
        }
    }
}

// ---------------------------------------------------------------------------
// GEMM3 + residual + SiLU -> NCHW fp32. M=1024 (grid.y=16, tile 64),
// N (grid.x=98), K=256, 4 chunks. Register epilogue, float2-paired x/out.
// ---------------------------------------------------------------------------
__global__ void __launch_bounds__(256, 3) gemm3_mma(const float* __restrict__ x,
                                                    float* __restrict__ out)
{
    extern __shared__ char smem[];
    const uint32_t sb = smem_u32(smem);
    const int tid = threadIdx.x, lane = tid & 31, wid = tid >> 5;
    const int wm = wid & 1, wn = wid >> 1;
    const int nbase = blockIdx.x * 128;
    const int mbase = blockIdx.y * 64;
    const int NCH = 4;

    const int row0 = tid >> 3, ch = tid & 7;
    const __half* srcA = g_w3h + (size_t)(mbase + row0) * WIDTH + ch * 8;
    const __half* srcB = g_u2 + (size_t)(nbase + row0) * WIDTH + ch * 8;
    const uint32_t dst0 = (uint32_t)(row0 * PITCH + ch * 16);

    float acc[2][4][4];
#pragma unroll
    for (int a = 0; a < 2; a++)
#pragma unroll
        for (int b = 0; b < 4; b++)
#pragma unroll
            for (int c = 0; c < 4; c++) acc[a][b][c] = 0.0f;

    auto prefetch = [&](int i) {
        const uint32_t base = sb + (i & 1) * STAGEB;
        const int koff = i * 64;
#pragma unroll
        for (int j = 0; j < 2; j++)
            cpa16(base + dst0 + j * (32 * PITCH), srcA + koff + j * (32 * WIDTH));
#pragma unroll
        for (int j = 0; j < 4; j++)
            cpa16(base + ATILEB + dst0 + j * (32 * PITCH), srcB + koff + j * (32 * WIDTH));
        CP_COMMIT();
    };

    prefetch(0);
    for (int i = 0; i < NCH; i++) {
        CP_WAIT0();
        __syncthreads();
        if (i + 1 < NCH) prefetch(i + 1);
        const uint32_t base = sb + (i & 1) * STAGEB;
        mma_chunk(base, base + ATILEB, wm, wn, lane, acc);
    }

#pragma unroll
    for (int mf = 0; mf < 2; mf++) {
#pragma unroll
        for (int half = 0; half < 2; half++) {
            const int o = mbase + wm * 32 + mf * 16 + (lane >> 2) + half * 8;
            const float sc = g_scale3[o], bi = g_bias3[o];
#pragma unroll
            for (int nf = 0; nf < 4; nf++) {
                const int n = nbase + wn * 32 + nf * 8 + (lane & 3) * 2;  // even
                const int b = n / HW, p = n - b * HW;                     // pair in-image
                const size_t idx = ((size_t)b * COUT + o) * HW + p;       // 8B aligned
                const float2 xv = *(const float2*)(x + idx);
                float2 ov;
                ov.x = silu_f(sc * acc[mf][nf][half * 2 + 0] + bi + xv.x);
                ov.y = silu_f(sc * acc[mf][nf][half * 2 + 1] + bi + xv.y);
                *(float2*)(out + idx) = ov;
            }
        }
    }
}

// ---------------------------------------------------------------------------
extern "C" void kernel_launch(void* const* d_in, const int* in_sizes, int n_in,
                              void* d_out, int out_size)
{
    const float* x   = (const float*)d_in[0];
    const float* w1  = (const float*)d_in[1];
    const float* b1  = (const float*)d_in[2];
    const float* g1  = (const float*)d_in[3];
    const float* be1 = (const float*)d_in[4];
    const float* m1  = (const float*)d_in[5];
    const float* v1  = (const float*)d_in[6];
    const float* w2  = (const float*)d_in[7];
    const float* b2  = (const float*)d_in[8];
    const float* g2  = (const float*)d_in[9];
    const float* be2 = (const float*)d_in[10];
    const float* m2  = (const float*)d_in[11];
    const float* v2  = (const float*)d_in[12];
    const float* w3  = (const float*)d_in[13];
    const float* b3  = (const float*)d_in[14];
    const float* g3  = (const float*)d_in[15];
    const float* be3 = (const float*)d_in[16];
    const float* m3  = (const float*)d_in[17];
    const float* v3  = (const float*)d_in[18];
    float* out = (float*)d_out;

    cudaFuncSetAttribute(prep_kernel, cudaFuncAttributeMaxDynamicSharedMemorySize, 50432);
    cudaFuncSetAttribute(gemm1_mma, cudaFuncAttributeMaxDynamicSharedMemorySize, SMEMB);
    cudaFuncSetAttribute(conv2_mma, cudaFuncAttributeMaxDynamicSharedMemorySize, C2SMEM);
    cudaFuncSetAttribute(gemm3_mma, cudaFuncAttributeMaxDynamicSharedMemorySize, SMEMB);

    prep_kernel<<<2560, 256, 50432>>>(x,
                                      w1, b1, g1, be1, m1, v1,
                                      w2, b2, g2, be2, m2, v2,
                                      w3, b3, g3, be3, m3, v3);

    gemm1_mma<<<dim3(98, 4), 256, SMEMB>>>();
    conv2_mma<<<dim3(128, 4), 256, C2SMEM>>>();
    gemm3_mma<<<dim3(98, 16), 256, SMEMB>>>(x, out);
}

// round 15
// speedup vs baseline: 1.0293x; 1.0293x over previous
#include <cuda_runtime.h>
#include <cuda_fp16.h>
#include <math.h>
#include <float.h>
#include <stdint.h>

// ---------------------------------------------------------------------------
// BottleneckBit via ldmatrix + mma.sync fp16 (base sm_103 target).
// R15: R13 structure (64x128 tiles, 3 CTAs/SM, compact conv2 w/ vmask,
// float2 gemm3 epilogue) + ldmatrix.x4 for B operands: two x4 loads replace
// four x2 loads per k-step (chunk instr count 56 -> 48).
// ---------------------------------------------------------------------------

#define BATCH 64
#define CIN   1024
#define WIDTH 256
#define COUT  1024
#define HW    196
#define NC    12544            // compact columns = 64*196 = 98*128

#define PITCH 144              // smem row: 64 fp16 (128B) + 16B pad
#define ATILEB (64*PITCH)      // 9216  (A: 64 rows)
#define BTILEB (128*PITCH)     // 18432 (B: 128 rows)
#define STAGEB (ATILEB+BTILEB) // 27648
#define SMEMB (2*STAGEB)       // 55296 (double buffered)

#define EPIPITCH 72            // halves per row (64 + 8 pad); 144B

__device__ __half g_w1h[WIDTH*CIN];         // [o][c]
__device__ __half g_w2h[9*WIDTH*WIDTH];     // [tap][o][c]
__device__ __half g_w3h[COUT*WIDTH];        // [o][c]
__device__ float g_scale1[WIDTH],  g_bias1[WIDTH];
__device__ float g_scale2[WIDTH],  g_bias2[WIDTH];
__device__ float g_scale3[COUT],   g_bias3[COUT];
__device__ __half g_xs[(size_t)NC*CIN];     // [n][c]
__device__ __half g_u1[(size_t)NC*WIDTH];   // [n][c]
__device__ __half g_u2[(size_t)NC*WIDTH];   // [n][c]

// ---------------------------------------------------------------------------
__device__ __forceinline__ uint32_t smem_u32(const void* p) {
    uint32_t a;
    asm("{ .reg .u64 t; cvta.to.shared.u64 t, %1; cvt.u32.u64 %0, t; }"
        : "=r"(a) : "l"(p));
    return a;
}
__device__ __forceinline__ void cpa16(uint32_t dst, const void* src) {
    asm volatile("cp.async.cg.shared.global [%0], [%1], 16;" :: "r"(dst), "l"(src));
}
__device__ __forceinline__ void cpa16z(uint32_t dst, const void* src, int sz) {
    asm volatile("cp.async.cg.shared.global [%0], [%1], 16, %2;"
                 :: "r"(dst), "l"(src), "r"(sz));
}
#define CP_COMMIT() asm volatile("cp.async.commit_group;" ::: "memory")
#define CP_WAIT0()  asm volatile("cp.async.wait_group 0;" ::: "memory")

__device__ __forceinline__ void ldm4(uint32_t* a, uint32_t addr) {
    asm volatile("ldmatrix.sync.aligned.m8n8.x4.shared.b16 {%0,%1,%2,%3}, [%4];"
                 : "=r"(a[0]), "=r"(a[1]), "=r"(a[2]), "=r"(a[3]) : "r"(addr));
}
__device__ __forceinline__ void mma16816(float* d, const uint32_t* a, const uint32_t* b) {
    asm volatile("mma.sync.aligned.m16n8k16.row.col.f32.f16.f16.f32 "
                 "{%0,%1,%2,%3}, {%4,%5,%6,%7}, {%8,%9}, {%0,%1,%2,%3};"
                 : "+f"(d[0]), "+f"(d[1]), "+f"(d[2]), "+f"(d[3])
                 : "r"(a[0]), "r"(a[1]), "r"(a[2]), "r"(a[3]), "r"(b[0]), "r"(b[1]));
}
__device__ __forceinline__ float silu_f(float x) { return x / (1.0f + expf(-x)); }

// one 64x128x64 chunk: warps 2(M) x 4(N), warp tile 32x32.
// A: 2 x ldmatrix.x4 (16 rows x 2 k-halves each).
// B: 2 x ldmatrix.x4 — lane-group g addresses matrix g:
//    groups 0/1 = rows nf*8 (k0,k16), groups 2/3 = rows (nf+1)*8 (k0,k16).
__device__ __forceinline__ void mma_chunk(uint32_t Abuf, uint32_t Bbuf,
                                          int wm, int wn, int lane,
                                          float acc[2][4][4])
{
    const uint32_t aRowSel = (uint32_t)(lane & 15) * PITCH + (uint32_t)(lane >> 4) * 16;
    const uint32_t bRowSel4 = (uint32_t)(lane & 7) * PITCH
                            + (uint32_t)((lane >> 3) & 1) * 16
                            + (uint32_t)(lane >> 4) * (8 * PITCH);
#pragma unroll
    for (int ks = 0; ks < 4; ks++) {
        uint32_t afr[2][4];
#pragma unroll
        for (int mf = 0; mf < 2; mf++)
            ldm4(afr[mf], Abuf + (uint32_t)(wm * 32 + mf * 16) * PITCH + ks * 32 + aRowSel);
        uint32_t bfr[4][2];
        ldm4(&bfr[0][0], Bbuf + (uint32_t)(wn * 32 + 0)  * PITCH + ks * 32 + bRowSel4);
        ldm4(&bfr[2][0], Bbuf + (uint32_t)(wn * 32 + 16) * PITCH + ks * 32 + bRowSel4);
#pragma unroll
        for (int mf = 0; mf < 2; mf++)
#pragma unroll
            for (int nf = 0; nf < 4; nf++)
                mma16816(acc[mf][nf], afr[mf], bfr[nf]);
    }
}

// smem-transpose epilogue: acc -> [n(128)][o(64)] half tile -> coalesced rows
__device__ __forceinline__ void epilogue_half(char* smem, int wm, int wn,
                                              int lane, int tid,
                                              int mbase, int nbase,
                                              const float* scale, const float* bias,
                                              float acc[2][4][4], __half* dst)
{
    __half* st = (__half*)smem;
#pragma unroll
    for (int mf = 0; mf < 2; mf++) {
#pragma unroll
        for (int half = 0; half < 2; half++) {
            const int ol = wm * 32 + mf * 16 + (lane >> 2) + half * 8;
            const float sc = scale[mbase + ol], bi = bias[mbase + ol];
#pragma unroll
            for (int nf = 0; nf < 4; nf++) {
#pragma unroll
                for (int cc = 0; cc < 2; cc++) {
                    int nrow = wn * 32 + nf * 8 + (lane & 3) * 2 + cc;
                    float sv = silu_f(sc * acc[mf][nf][half * 2 + cc] + bi);
                    st[nrow * EPIPITCH + ol] = __float2half_rn(sv);
                }
            }
        }
    }
    __syncthreads();
    const int nrow = tid >> 1, off = (tid & 1) * 32;   // halves
    const uint4* s4 = (const uint4*)(st + nrow * EPIPITCH + off);
    uint4* d4 = (uint4*)(dst + (size_t)(nbase + nrow) * WIDTH + mbase + off);
#pragma unroll
    for (int k = 0; k < 4; k++) d4[k] = s4[k];
}

// ---------------------------------------------------------------------------
// prep: blocks [0,1536) quantize weights, blocks [1536,2560) convert x->fp16.
// ---------------------------------------------------------------------------
__global__ void __launch_bounds__(256) prep_kernel(
    const float* __restrict__ x,
    const float* __restrict__ w1, const float* __restrict__ b1,
    const float* __restrict__ g1, const float* __restrict__ be1,
    const float* __restrict__ m1, const float* __restrict__ v1,
    const float* __restrict__ w2, const float* __restrict__ b2,
    const float* __restrict__ g2, const float* __restrict__ be2,
    const float* __restrict__ m2, const float* __restrict__ v2,
    const float* __restrict__ w3, const float* __restrict__ b3,
    const float* __restrict__ g3, const float* __restrict__ be3,
    const float* __restrict__ m3, const float* __restrict__ v3)
{
    const int blk = blockIdx.x;
    const int tid = threadIdx.x;

    if (blk >= 1536) {
        // ---- xconv part ----
        extern __shared__ float s[];
        const int idx = blk - 1536;
        const int b = idx >> 4, cb = idx & 15;
        const float* xp = x + ((size_t)b * CIN + cb * 64) * HW;
        for (int i = tid; i < 64 * HW; i += 256) {
            int ci = i / HW, p = i - ci * HW;
            s[ci * 197 + p] = xp[(size_t)ci * HW + p];
        }
        __syncthreads();
        const int coff = tid & 63;
        for (int p = tid >> 6; p < HW; p += 4) {
            int n = b * HW + p;
            g_xs[(size_t)n * CIN + cb * 64 + coff] = __float2half_rn(s[coff * 197 + p]);
        }
        return;
    }

    // ---- quant part ----
    __shared__ int scnt0, scnt1;
    int which, o, K;
    const float *w, *bc, *g, *be, *m, *v;
    if (blk < 256)      { which = 1; o = blk;       K = 1024; w = w1; bc = b1; g = g1; be = be1; m = m1; v = v1; }
    else if (blk < 512) { which = 2; o = blk - 256; K = 2304; w = w2; bc = b2; g = g2; be = be2; m = m2; v = v2; }
    else                { which = 3; o = blk - 512; K = 256;  w = w3; bc = b3; g = g3; be = be3; m = m3; v = v3; }

    const float* wrow = w + (size_t)o * K;
    uint32_t vals[9];
    const int nv = (K + 255) / 256;
    for (int j = 0; j < nv; j++) {
        int idx = tid + j * 256;
        vals[j] = (idx < K) ? __float_as_uint(fabsf(wrow[idx])) : 0xffffffffu;
    }

    const int k0 = K / 2 - 1, k1 = K / 2;
    uint32_t lo0 = 0, hi0 = 0x7f7fffffu, lo1 = 0, hi1 = 0x7f7fffffu;
    while (lo0 < hi0 || lo1 < hi1) {
        uint32_t mid0 = lo0 + ((hi0 - lo0) >> 1);
        uint32_t mid1 = lo1 + ((hi1 - lo1) >> 1);
        __syncthreads();
        if (tid == 0) { scnt0 = 0; scnt1 = 0; }
        __syncthreads();
        int c0 = 0, c1 = 0;
        for (int j = 0; j < nv; j++) {
            c0 += (vals[j] <= mid0) ? 1 : 0;
            c1 += (vals[j] <= mid1) ? 1 : 0;
        }
#pragma unroll
        for (int off = 16; off; off >>= 1) {
            c0 += __shfl_down_sync(~0u, c0, off);
            c1 += __shfl_down_sync(~0u, c1, off);
        }
        if ((tid & 31) == 0) { atomicAdd(&scnt0, c0); atomicAdd(&scnt1, c1); }
        __syncthreads();
        if (lo0 < hi0) { if (scnt0 >= k0 + 1) hi0 = mid0; else lo0 = mid0 + 1; }
        if (lo1 < hi1) { if (scnt1 >= k1 + 1) hi1 = mid1; else lo1 = mid1 + 1; }
    }
    const float med = 0.5f * (__uint_as_float(lo0) + __uint_as_float(lo1));
    const float sc = fmaxf(med, 1e-8f);
    const float alpha = g[o] / sqrtf(v[o] + 1e-5f);

    for (int i = tid; i < K; i += 256) {
        float q = rintf(wrow[i] / sc);
        q = fminf(fmaxf(q, -1.0f), 1.0f);
        __half t = __float2half_rn(q);          // exact ternary
        if (which == 1)      g_w1h[(size_t)o * CIN + i] = t;
        else if (which == 3) g_w3h[(size_t)o * WIDTH + i] = t;
        else {
            int c = i / 9, tap = i - c * 9;
            g_w2h[((size_t)tap * WIDTH + o) * WIDTH + c] = t;
        }
    }
    if (tid == 0) {
        float scal = sc * alpha;
        float bias = bc[o] * alpha + be[o] - m[o] * alpha;
        if (which == 1)      { g_scale1[o] = scal; g_bias1[o] = bias; }
        else if (which == 2) { g_scale2[o] = scal; g_bias2[o] = bias; }
        else                 { g_scale3[o] = scal; g_bias3[o] = bias; }
    }
}

// ---------------------------------------------------------------------------
// GEMM1: M=256 (grid.y=4, tile 64), N=12544 (grid.x=98), K=1024, 16 chunks.
// ---------------------------------------------------------------------------
__global__ void __launch_bounds__(256, 3) gemm1_mma()
{
    extern __shared__ char smem[];
    const uint32_t sb = smem_u32(smem);
    const int tid = threadIdx.x, lane = tid & 31, wid = tid >> 5;
    const int wm = wid & 1, wn = wid >> 1;
    const int nbase = blockIdx.x * 128;
    const int mbase = blockIdx.y * 64;
    const int NCH = 16;

    const int row0 = tid >> 3, ch = tid & 7;
    const __half* srcA = g_w1h + (size_t)(mbase + row0) * CIN + ch * 8;
    const __half* srcB = g_xs + (size_t)(nbase + row0) * CIN + ch * 8;
    const uint32_t dst0 = (uint32_t)(row0 * PITCH + ch * 16);

    float acc[2][4][4];
#pragma unroll
    for (int a = 0; a < 2; a++)
#pragma unroll
        for (int b = 0; b < 4; b++)
#pragma unroll
            for (int c = 0; c < 4; c++) acc[a][b][c] = 0.0f;

    auto prefetch = [&](int i) {
        const uint32_t base = sb + (i & 1) * STAGEB;
        const int koff = i * 64;
#pragma unroll
        for (int j = 0; j < 2; j++)
            cpa16(base + dst0 + j * (32 * PITCH), srcA + koff + j * (32 * CIN));
#pragma unroll
        for (int j = 0; j < 4; j++)
            cpa16(base + ATILEB + dst0 + j * (32 * PITCH), srcB + koff + j * (32 * CIN));
        CP_COMMIT();
    };

    prefetch(0);
    for (int i = 0; i < NCH; i++) {
        CP_WAIT0();
        __syncthreads();
        if (i + 1 < NCH) prefetch(i + 1);
        const uint32_t base = sb + (i & 1) * STAGEB;
        mma_chunk(base, base + ATILEB, wm, wn, lane, acc);
    }
    // last chunk computed from buf1; epilogue tile fits in buf0.
    epilogue_half(smem, wm, wn, lane, tid, mbase, nbase, g_scale1, g_bias1, acc, g_u1);
}

// ---------------------------------------------------------------------------
// CONV2: N (grid.x=98), M=256 (grid.y=4, tile 64), 9 taps x 4 k-chunks = 36.
// ---------------------------------------------------------------------------
__global__ void __launch_bounds__(256, 3) conv2_mma()
{
    extern __shared__ char smem[];
    const uint32_t sb = smem_u32(smem);
    const int tid = threadIdx.x, lane = tid & 31, wid = tid >> 5;
    const int wm = wid & 1, wn = wid >> 1;
    const int nbase = blockIdx.x * 128;
    const int mbase = blockIdx.y * 64;
    const int NCH = 36;

    const int row0 = tid >> 3, ch = tid & 7;
    const __half* srcA = g_w2h + (size_t)(mbase + row0) * WIDTH + ch * 8;
    const uint32_t dst0 = (uint32_t)(row0 * PITCH + ch * 16);
    // per-j source base and 9-bit tap validity mask (bit tap)
    const __half* srcB0[4];
    uint32_t vmask[4];
#pragma unroll
    for (int j = 0; j < 4; j++) {
        int n = nbase + row0 + 32 * j;
        int b = n / HW, p = n - b * HW;
        int pr = p / 14, pc = p - pr * 14;
        srcB0[j] = g_u1 + (size_t)n * WIDTH + ch * 8;
        uint32_t msk = 0;
#pragma unroll
        for (int tap = 0; tap < 9; tap++) {
            int dh = tap / 3 - 1, dw = tap - (tap / 3) * 3 - 1;
            if (((unsigned)(pr + dh) < 14u) && ((unsigned)(pc + dw) < 14u))
                msk |= (1u << tap);
        }
        vmask[j] = msk;
    }

    float acc[2][4][4];
#pragma unroll
    for (int a = 0; a < 2; a++)
#pragma unroll
        for (int b = 0; b < 4; b++)
#pragma unroll
            for (int c = 0; c < 4; c++) acc[a][b][c] = 0.0f;

    auto prefetch = [&](int i) {
        const uint32_t base = sb + (i & 1) * STAGEB;
        const int tap = i >> 2, kc = i & 3;
        const int dh = tap / 3 - 1, dw = tap - (tap / 3) * 3 - 1;
        const int boff = (dh * 14 + dw) * WIDTH + kc * 64;
        const size_t aoff = (size_t)tap * (WIDTH * WIDTH) + kc * 64;
#pragma unroll
        for (int j = 0; j < 2; j++)
            cpa16(base + dst0 + j * (32 * PITCH), srcA + aoff + j * (32 * WIDTH));
#pragma unroll
        for (int j = 0; j < 4; j++) {
            bool valid = (vmask[j] >> tap) & 1;
            const __half* src = valid ? (srcB0[j] + boff) : g_u1;
            cpa16z(base + ATILEB + dst0 + j * (32 * PITCH), src, valid ? 16 : 0);
        }
        CP_COMMIT();
    };

    prefetch(0);
    for (int i = 0; i < NCH; i++) {
        CP_WAIT0();
        __syncthreads();
        if (i + 1 < NCH) prefetch(i + 1);
        const uint32_t base = sb + (i & 1) * STAGEB;
        mma_chunk(base, base + ATILEB, wm, wn, lane, acc);
    }
    epilogue_half(smem, wm, wn, lane, tid, mbase, nbase, g_scale2, g_bias2, acc, g_u2);
}

// ---------------------------------------------------------------------------
// GEMM3 + residual + SiLU -> NCHW fp32. M=1024 (grid.y=16, tile 64),
// N (grid.x=98), K=256, 4 chunks. Register epilogue with float2-paired
// residual loads and output stores (n pairs even, never straddle an image).
// ---------------------------------------------------------------------------
__global__ void __launch_bounds__(256, 3) gemm3_mma(const float* __restrict__ x,
                                                    float* __restrict__ out)
{
    extern __shared__ char smem[];
    const uint32_t sb = smem_u32(smem);
    const int tid = threadIdx.x, lane = tid & 31, wid = tid >> 5;
    const int wm = wid & 1, wn = wid >> 1;
    const int nbase = blockIdx.x * 128;
    const int mbase = blockIdx.y * 64;
    const int NCH = 4;

    const int row0 = tid >> 3, ch = tid & 7;
    const __half* srcA = g_w3h + (size_t)(mbase + row0) * WIDTH + ch * 8;
    const __half* srcB = g_u2 + (size_t)(nbase + row0) * WIDTH + ch * 8;
    const uint32_t dst0 = (uint32_t)(row0 * PITCH + ch * 16);

    float acc[2][4][4];
#pragma unroll
    for (int a = 0; a < 2; a++)
#pragma unroll
        for (int b = 0; b < 4; b++)
#pragma unroll
            for (int c = 0; c < 4; c++) acc[a][b][c] = 0.0f;

    auto prefetch = [&](int i) {
        const uint32_t base = sb + (i & 1) * STAGEB;
        const int koff = i * 64;
#pragma unroll
        for (int j = 0; j < 2; j++)
            cpa16(base + dst0 + j * (32 * PITCH), srcA + koff + j * (32 * WIDTH));
#pragma unroll
        for (int j = 0; j < 4; j++)
            cpa16(base + ATILEB + dst0 + j * (32 * PITCH), srcB + koff + j * (32 * WIDTH));
        CP_COMMIT();
    };

    prefetch(0);
    for (int i = 0; i < NCH; i++) {
        CP_WAIT0();
        __syncthreads();
        if (i + 1 < NCH) prefetch(i + 1);
        const uint32_t base = sb + (i & 1) * STAGEB;
        mma_chunk(base, base + ATILEB, wm, wn, lane, acc);
    }

#pragma unroll
    for (int mf = 0; mf < 2; mf++) {
#pragma unroll
        for (int half = 0; half < 2; half++) {
            const int o = mbase + wm * 32 + mf * 16 + (lane >> 2) + half * 8;
            const float sc = g_scale3[o], bi = g_bias3[o];
#pragma unroll
            for (int nf = 0; nf < 4; nf++) {
                const int n = nbase + wn * 32 + nf * 8 + (lane & 3) * 2;  // even
                const int b = n / HW, p = n - b * HW;                     // pair in-image
                const size_t idx = ((size_t)b * COUT + o) * HW + p;       // 8B aligned
                const float2 xv = *(const float2*)(x + idx);
                float2 ov;
                ov.x = silu_f(sc * acc[mf][nf][half * 2 + 0] + bi + xv.x);
                ov.y = silu_f(sc * acc[mf][nf][half * 2 + 1] + bi + xv.y);
                *(float2*)(out + idx) = ov;
            }
        }
    }
}

// ---------------------------------------------------------------------------
extern "C" void kernel_launch(void* const* d_in, const int* in_sizes, int n_in,
                              void* d_out, int out_size)
{
    const float* x   = (const float*)d_in[0];
    const float* w1  = (const float*)d_in[1];
    const float* b1  = (const float*)d_in[2];
    const float* g1  = (const float*)d_in[3];
    const float* be1 = (const float*)d_in[4];
    const float* m1  = (const float*)d_in[5];
    const float* v1  = (const float*)d_in[6];
    const float* w2  = (const float*)d_in[7];
    const float* b2  = (const float*)d_in[8];
    const float* g2  = (const float*)d_in[9];
    const float* be2 = (const float*)d_in[10];
    const float* m2  = (const float*)d_in[11];
    const float* v2  = (const float*)d_in[12];
    const float* w3  = (const float*)d_in[13];
    const float* b3  = (const float*)d_in[14];
    const float* g3  = (const float*)d_in[15];
    const float* be3 = (const float*)d_in[16];
    const float* m3  = (const float*)d_in[17];
    const float* v3  = (const float*)d_in[18];
    float* out = (float*)d_out;

    cudaFuncSetAttribute(prep_kernel, cudaFuncAttributeMaxDynamicSharedMemorySize, 50432);
    cudaFuncSetAttribute(gemm1_mma, cudaFuncAttributeMaxDynamicSharedMemorySize, SMEMB);
    cudaFuncSetAttribute(conv2_mma, cudaFuncAttributeMaxDynamicSharedMemorySize, SMEMB);
    cudaFuncSetAttribute(gemm3_mma, cudaFuncAttributeMaxDynamicSharedMemorySize, SMEMB);

    prep_kernel<<<2560, 256, 50432>>>(x,
                                      w1, b1, g1, be1, m1, v1,
                                      w2, b2, g2, be2, m2, v2,
                                      w3, b3, g3, be3, m3, v3);

    gemm1_mma<<<dim3(98, 4), 256, SMEMB>>>();
    conv2_mma<<<dim3(98, 4), 256, SMEMB>>>();
    gemm3_mma<<<dim3(98, 16), 256, SMEMB>>>(x, out);
}